// round 14
// baseline (speedup 1.0000x reference)
#include <cuda_runtime.h>

// Problem constants
#define NROWS   (128 * 2048)       // 262144 rows
#define DD      64                 // embedding dim
#define KK      512                // codebook size
#define EPSF    1e-7f
#define GRID    148                // one block per SM (persistent wave)
#define TPB     256

#define SMEM_W_FLOATS (KK * DD)                          // 32768 floats = 128 KB
#define SMEM_FLOATS   (SMEM_W_FLOATS + KK + TPB)         // + wsq + reduce buffer
#define SMEM_BYTES    (SMEM_FLOATS * 4)

__device__ float g_partial[GRID];

// ---- packed f32x2 helpers (ptxas never auto-fuses; PTX only) ----
__device__ __forceinline__ unsigned long long pack2(float lo, float hi) {
    unsigned long long u;
    asm("mov.b64 %0, {%1, %2};" : "=l"(u) : "f"(lo), "f"(hi));
    return u;
}
__device__ __forceinline__ void unpack2(unsigned long long u, float& lo, float& hi) {
    asm("mov.b64 {%0, %1}, %2;" : "=f"(lo), "=f"(hi) : "l"(u));
}
__device__ __forceinline__ void ffma2(unsigned long long& d, unsigned long long a, unsigned long long b) {
    asm("fma.rn.f32x2 %0, %1, %2, %3;" : "=l"(d) : "l"(a), "l"(b), "l"(d));
}
__device__ __forceinline__ unsigned long long fadd2(unsigned long long a, unsigned long long b) {
    unsigned long long d;
    asm("add.rn.f32x2 %0, %1, %2;" : "=l"(d) : "l"(a), "l"(b));
    return d;
}

__global__ void __launch_bounds__(TPB, 1)
vq_main(const float* __restrict__ x, const float* __restrict__ W, float* __restrict__ out)
{
    extern __shared__ float smem[];
    float* sW   = smem;                     // [KK*DD]
    float* swsq = smem + SMEM_W_FLOATS;     // [KK]
    float* sred = swsq + KK;                // [TPB]

    const int tid = threadIdx.x;

    // Stage codebook into shared memory (vectorized)
    {
        const float4* Wv = (const float4*)W;
        float4* sWv = (float4*)sW;
        #pragma unroll 4
        for (int i = tid; i < SMEM_W_FLOATS / 4; i += TPB) sWv[i] = Wv[i];
    }
    __syncthreads();
    // Precompute ||W_k||^2 (sequential fp32 sum; b_k error ~1e-11, far below
    // the ulp(63)=3.8e-6 quantization grid that decides argmin ties)
    for (int k = tid; k < KK; k += TPB) {
        float s = 0.f;
        #pragma unroll
        for (int d = 0; d < DD; d++) { float w = sW[k * DD + d]; s = fmaf(w, w, s); }
        swsq[k] = s;
    }
    __syncthreads();

    float* outq   = out;
    float* outidx = out + (size_t)NROWS * DD + 1;

    float lsum_total = 0.f;

    for (int row = blockIdx.x * TPB + tid; row < NROWS; row += GRID * TPB) {
        // ---- load row, compute mean / unbiased std (two-pass, like reference) ----
        const float4* xr = (const float4*)(x + (size_t)row * DD);
        float4 v[16];
        float sum = 0.f;
        #pragma unroll
        for (int j = 0; j < 16; j++) {
            v[j] = xr[j];
            sum += (v[j].x + v[j].y) + (v[j].z + v[j].w);
        }
        float mean = sum * (1.0f / 64.0f);
        float sumd2 = 0.f;
        #pragma unroll
        for (int j = 0; j < 16; j++) {
            float d0 = v[j].x - mean, d1 = v[j].y - mean;
            float d2 = v[j].z - mean, d3 = v[j].w - mean;
            sumd2 = fmaf(d0, d0, sumd2);
            sumd2 = fmaf(d1, d1, sumd2);
            sumd2 = fmaf(d2, d2, sumd2);
            sumd2 = fmaf(d3, d3, sumd2);
        }
        float var    = __fdiv_rn(sumd2, 63.0f);          // ddof=1
        float stdev  = __fsqrt_rn(var);                   // IEEE sqrt
        float denorm = __fadd_rn(stdev, EPSF);
        float inv    = __frcp_rn(denorm);                 // precise reciprocal

        // ---- normalized row packed as 32 f32x2 regs; A = ||xn||^2 ----
        unsigned long long xn2[32];
        float A = 0.f;
        #pragma unroll
        for (int j = 0; j < 16; j++) {
            float x0 = (v[j].x - mean) * inv;
            float x1 = (v[j].y - mean) * inv;
            float x2 = (v[j].z - mean) * inv;
            float x3 = (v[j].w - mean) * inv;
            A = fmaf(x0, x0, A);
            A = fmaf(x1, x1, A);
            A = fmaf(x2, x2, A);
            A = fmaf(x3, x3, A);
            xn2[2 * j]     = pack2(x0, x1);
            xn2[2 * j + 1] = pack2(x2, x3);
        }

        // ---- argmin over 512 codes, emulating reference rounding:
        //      d_k = fl( fl(A + ||W_k||^2) - fl(2 * xn.W_k) )
        //      (explicit _rn intrinsics: no FMA contraction allowed here)
        float best = 3.4e38f;
        int   bi   = 0;
        const ulonglong2* sW2 = (const ulonglong2*)sW;
        for (int k = 0; k < KK; k++) {
            unsigned long long a0 = 0ull, a1 = 0ull, a2 = 0ull, a3 = 0ull;
            const ulonglong2* wp = sW2 + k * (DD / 4);
            #pragma unroll
            for (int j = 0; j < 16; j += 2) {
                ulonglong2 wA = wp[j];       // 4 floats, LDS.128 broadcast
                ulonglong2 wB = wp[j + 1];
                ffma2(a0, xn2[2 * j],     wA.x);
                ffma2(a1, xn2[2 * j + 1], wA.y);
                ffma2(a2, xn2[2 * j + 2], wB.x);
                ffma2(a3, xn2[2 * j + 3], wB.y);
            }
            unsigned long long s = fadd2(fadd2(a0, a1), fadd2(a2, a3));
            float lo, hi; unpack2(s, lo, hi);
            float dot   = __fadd_rn(lo, hi);
            float Xk    = __fadd_rn(A, swsq[k]);          // fl(A + b_k)
            float dk    = __fsub_rn(Xk, __fmul_rn(2.0f, dot));  // fl(X - 2c)
            if (dk < best) { best = dk; bi = k; }         // first-min on ties
        }

        // ---- epilogue: quantized output, local loss, index ----
        const float4* wq = (const float4*)(sW + bi * DD);
        float4* oq = (float4*)(outq + (size_t)row * DD);
        float lsum = 0.f;
        #pragma unroll
        for (int j = 0; j < 16; j++) {
            float4 w = wq[j];
            float x0, x1, x2, x3;
            unpack2(xn2[2 * j],     x0, x1);
            unpack2(xn2[2 * j + 1], x2, x3);
            float d0 = w.x - x0, d1 = w.y - x1, d2 = w.z - x2, d3 = w.w - x3;
            lsum = fmaf(d0, d0, lsum);
            lsum = fmaf(d1, d1, lsum);
            lsum = fmaf(d2, d2, lsum);
            lsum = fmaf(d3, d3, lsum);
            float4 o;
            o.x = fmaf(w.x, denorm, mean);
            o.y = fmaf(w.y, denorm, mean);
            o.z = fmaf(w.z, denorm, mean);
            o.w = fmaf(w.w, denorm, mean);
            oq[j] = o;
        }
        lsum_total += lsum;
        outidx[row] = (float)bi;
    }

    // ---- deterministic block reduction of loss partials ----
    sred[tid] = lsum_total;
    __syncthreads();
    for (int s = TPB / 2; s > 0; s >>= 1) {
        if (tid < s) sred[tid] += sred[tid + s];
        __syncthreads();
    }
    if (tid == 0) g_partial[blockIdx.x] = sred[0];
}

__global__ void vq_loss(float* __restrict__ out)
{
    // single-thread deterministic reduction of 148 partials in double
    double t = 0.0;
    #pragma unroll 1
    for (int i = 0; i < GRID; i++) t += (double)g_partial[i];
    out[(size_t)NROWS * DD] = (float)(1.25 * t / (double)((size_t)NROWS * DD));
}

extern "C" void kernel_launch(void* const* d_in, const int* in_sizes, int n_in,
                              void* d_out, int out_size)
{
    const float* x = (const float*)d_in[0];
    const float* W = (const float*)d_in[1];
    float* out = (float*)d_out;

    cudaFuncSetAttribute(vq_main, cudaFuncAttributeMaxDynamicSharedMemorySize, SMEM_BYTES);
    vq_main<<<GRID, TPB, SMEM_BYTES>>>(x, W, out);
    vq_loss<<<1, 1>>>(out);
}

// round 15
// speedup vs baseline: 1.0005x; 1.0005x over previous
#include <cuda_runtime.h>

// Problem constants
#define NROWS   (128 * 2048)       // 262144 rows
#define DD      64                 // embedding dim
#define KK      512                // codebook size
#define EPSF    1e-7f
#define GRID    148                // one block per SM (persistent wave)
#define TPB     256

#define SMEM_W_FLOATS (KK * DD)                          // 32768 floats = 128 KB
#define SMEM_FLOATS   (SMEM_W_FLOATS + KK + TPB)         // + wsq + reduce buffer
#define SMEM_BYTES    (SMEM_FLOATS * 4)

__device__ float g_partial[GRID];

// ---- packed f32x2 helpers (ptxas never auto-fuses; PTX only) ----
__device__ __forceinline__ unsigned long long pack2(float lo, float hi) {
    unsigned long long u;
    asm("mov.b64 %0, {%1, %2};" : "=l"(u) : "f"(lo), "f"(hi));
    return u;
}
__device__ __forceinline__ void unpack2(unsigned long long u, float& lo, float& hi) {
    asm("mov.b64 {%0, %1}, %2;" : "=f"(lo), "=f"(hi) : "l"(u));
}
__device__ __forceinline__ void ffma2(unsigned long long& d, unsigned long long a, unsigned long long b) {
    asm("fma.rn.f32x2 %0, %1, %2, %3;" : "=l"(d) : "l"(a), "l"(b), "l"(d));
}
__device__ __forceinline__ unsigned long long fadd2(unsigned long long a, unsigned long long b) {
    unsigned long long d;
    asm("add.rn.f32x2 %0, %1, %2;" : "=l"(d) : "l"(a), "l"(b));
    return d;
}

__global__ void __launch_bounds__(TPB, 1)
vq_main(const float* __restrict__ x, const float* __restrict__ W, float* __restrict__ out)
{
    extern __shared__ float smem[];
    float* sW   = smem;                     // [KK*DD]
    float* swsq = smem + SMEM_W_FLOATS;     // [KK]
    float* sred = swsq + KK;                // [TPB]

    const int tid = threadIdx.x;

    // Stage codebook into shared memory (vectorized)
    {
        const float4* Wv = (const float4*)W;
        float4* sWv = (float4*)sW;
        #pragma unroll 4
        for (int i = tid; i < SMEM_W_FLOATS / 4; i += TPB) sWv[i] = Wv[i];
    }
    __syncthreads();
    // Precompute ||W_k||^2 (sequential fp32 sum; b_k error ~1e-11, far below
    // the ulp(63)=3.8e-6 quantization grid that decides argmin ties)
    for (int k = tid; k < KK; k += TPB) {
        float s = 0.f;
        #pragma unroll
        for (int d = 0; d < DD; d++) { float w = sW[k * DD + d]; s = fmaf(w, w, s); }
        swsq[k] = s;
    }
    __syncthreads();

    float* outq   = out;
    float* outidx = out + (size_t)NROWS * DD + 1;

    float lsum_total = 0.f;

    for (int row = blockIdx.x * TPB + tid; row < NROWS; row += GRID * TPB) {
        // ---- load row, compute mean / unbiased std (two-pass, like reference) ----
        const float4* xr = (const float4*)(x + (size_t)row * DD);
        float4 v[16];
        float sum = 0.f;
        #pragma unroll
        for (int j = 0; j < 16; j++) {
            v[j] = xr[j];
            sum += (v[j].x + v[j].y) + (v[j].z + v[j].w);
        }
        float mean = sum * (1.0f / 64.0f);
        float sumd2 = 0.f;
        #pragma unroll
        for (int j = 0; j < 16; j++) {
            float d0 = v[j].x - mean, d1 = v[j].y - mean;
            float d2 = v[j].z - mean, d3 = v[j].w - mean;
            sumd2 = fmaf(d0, d0, sumd2);
            sumd2 = fmaf(d1, d1, sumd2);
            sumd2 = fmaf(d2, d2, sumd2);
            sumd2 = fmaf(d3, d3, sumd2);
        }
        float var    = __fdiv_rn(sumd2, 63.0f);          // ddof=1
        float stdev  = __fsqrt_rn(var);                   // IEEE sqrt
        float denorm = __fadd_rn(stdev, EPSF);
        float inv    = __frcp_rn(denorm);                 // precise reciprocal

        // ---- normalized row packed as 32 f32x2 regs; A = ||xn||^2 ----
        unsigned long long xn2[32];
        float A = 0.f;
        #pragma unroll
        for (int j = 0; j < 16; j++) {
            float x0 = (v[j].x - mean) * inv;
            float x1 = (v[j].y - mean) * inv;
            float x2 = (v[j].z - mean) * inv;
            float x3 = (v[j].w - mean) * inv;
            A = fmaf(x0, x0, A);
            A = fmaf(x1, x1, A);
            A = fmaf(x2, x2, A);
            A = fmaf(x3, x3, A);
            xn2[2 * j]     = pack2(x0, x1);
            xn2[2 * j + 1] = pack2(x2, x3);
        }

        // ---- argmin over 512 codes, emulating reference rounding:
        //      d_k = fl( fl(A + ||W_k||^2) - fl(2 * xn.W_k) )
        //      (explicit _rn intrinsics: no FMA contraction allowed here)
        float best = 3.4e38f;
        int   bi   = 0;
        const ulonglong2* sW2 = (const ulonglong2*)sW;
        for (int k = 0; k < KK; k++) {
            unsigned long long a0 = 0ull, a1 = 0ull, a2 = 0ull, a3 = 0ull;
            const ulonglong2* wp = sW2 + k * (DD / 4);
            #pragma unroll
            for (int j = 0; j < 16; j += 2) {
                ulonglong2 wA = wp[j];       // 4 floats, LDS.128 broadcast
                ulonglong2 wB = wp[j + 1];
                ffma2(a0, xn2[2 * j],     wA.x);
                ffma2(a1, xn2[2 * j + 1], wA.y);
                ffma2(a2, xn2[2 * j + 2], wB.x);
                ffma2(a3, xn2[2 * j + 3], wB.y);
            }
            unsigned long long s = fadd2(fadd2(a0, a1), fadd2(a2, a3));
            float lo, hi; unpack2(s, lo, hi);
            float dot   = __fadd_rn(lo, hi);
            float Xk    = __fadd_rn(A, swsq[k]);          // fl(A + b_k)
            float dk    = __fsub_rn(Xk, __fmul_rn(2.0f, dot));  // fl(X - 2c)
            if (dk < best) { best = dk; bi = k; }         // first-min on ties
        }

        // ---- epilogue: quantized output, local loss, index ----
        const float4* wq = (const float4*)(sW + bi * DD);
        float4* oq = (float4*)(outq + (size_t)row * DD);
        float lsum = 0.f;
        #pragma unroll
        for (int j = 0; j < 16; j++) {
            float4 w = wq[j];
            float x0, x1, x2, x3;
            unpack2(xn2[2 * j],     x0, x1);
            unpack2(xn2[2 * j + 1], x2, x3);
            float d0 = w.x - x0, d1 = w.y - x1, d2 = w.z - x2, d3 = w.w - x3;
            lsum = fmaf(d0, d0, lsum);
            lsum = fmaf(d1, d1, lsum);
            lsum = fmaf(d2, d2, lsum);
            lsum = fmaf(d3, d3, lsum);
            float4 o;
            o.x = fmaf(w.x, denorm, mean);
            o.y = fmaf(w.y, denorm, mean);
            o.z = fmaf(w.z, denorm, mean);
            o.w = fmaf(w.w, denorm, mean);
            oq[j] = o;
        }
        lsum_total += lsum;
        outidx[row] = (float)bi;
    }

    // ---- deterministic block reduction of loss partials ----
    sred[tid] = lsum_total;
    __syncthreads();
    for (int s = TPB / 2; s > 0; s >>= 1) {
        if (tid < s) sred[tid] += sred[tid + s];
        __syncthreads();
    }
    if (tid == 0) g_partial[blockIdx.x] = sred[0];
}

__global__ void vq_loss(float* __restrict__ out)
{
    // single-thread deterministic reduction of 148 partials in double
    double t = 0.0;
    #pragma unroll 1
    for (int i = 0; i < GRID; i++) t += (double)g_partial[i];
    out[(size_t)NROWS * DD] = (float)(1.25 * t / (double)((size_t)NROWS * DD));
}

extern "C" void kernel_launch(void* const* d_in, const int* in_sizes, int n_in,
                              void* d_out, int out_size)
{
    const float* x = (const float*)d_in[0];
    const float* W = (const float*)d_in[1];
    float* out = (float*)d_out;

    cudaFuncSetAttribute(vq_main, cudaFuncAttributeMaxDynamicSharedMemorySize, SMEM_BYTES);
    vq_main<<<GRID, TPB, SMEM_BYTES>>>(x, W, out);
    vq_loss<<<1, 1>>>(out);
}

// round 16
// speedup vs baseline: 1.0035x; 1.0030x over previous
#include <cuda_runtime.h>

// Problem constants
#define NROWS   (128 * 2048)       // 262144 rows
#define DD      64                 // embedding dim
#define KK      512                // codebook size
#define EPSF    1e-7f
#define GRID    148                // one block per SM (persistent wave)
#define TPB     256

#define SMEM_W_FLOATS (KK * DD)                          // 32768 floats = 128 KB
#define SMEM_FLOATS   (SMEM_W_FLOATS + KK + TPB)         // + wsq + reduce buffer
#define SMEM_BYTES    (SMEM_FLOATS * 4)

__device__ float g_partial[GRID];

// ---- packed f32x2 helpers (ptxas never auto-fuses; PTX only) ----
__device__ __forceinline__ unsigned long long pack2(float lo, float hi) {
    unsigned long long u;
    asm("mov.b64 %0, {%1, %2};" : "=l"(u) : "f"(lo), "f"(hi));
    return u;
}
__device__ __forceinline__ void unpack2(unsigned long long u, float& lo, float& hi) {
    asm("mov.b64 {%0, %1}, %2;" : "=f"(lo), "=f"(hi) : "l"(u));
}
__device__ __forceinline__ void ffma2(unsigned long long& d, unsigned long long a, unsigned long long b) {
    asm("fma.rn.f32x2 %0, %1, %2, %3;" : "=l"(d) : "l"(a), "l"(b), "l"(d));
}
__device__ __forceinline__ unsigned long long fadd2(unsigned long long a, unsigned long long b) {
    unsigned long long d;
    asm("add.rn.f32x2 %0, %1, %2;" : "=l"(d) : "l"(a), "l"(b));
    return d;
}

__global__ void __launch_bounds__(TPB, 1)
vq_main(const float* __restrict__ x, const float* __restrict__ W, float* __restrict__ out)
{
    extern __shared__ float smem[];
    float* sW   = smem;                     // [KK*DD]
    float* swsq = smem + SMEM_W_FLOATS;     // [KK]
    float* sred = swsq + KK;                // [TPB]

    const int tid = threadIdx.x;

    // Stage codebook into shared memory (vectorized)
    {
        const float4* Wv = (const float4*)W;
        float4* sWv = (float4*)sW;
        #pragma unroll 4
        for (int i = tid; i < SMEM_W_FLOATS / 4; i += TPB) sWv[i] = Wv[i];
    }
    __syncthreads();
    // Precompute ||W_k||^2 (sequential fp32 sum; b_k error ~1e-11, far below
    // the ulp(63)=3.8e-6 quantization grid that decides argmin ties)
    for (int k = tid; k < KK; k += TPB) {
        float s = 0.f;
        #pragma unroll
        for (int d = 0; d < DD; d++) { float w = sW[k * DD + d]; s = fmaf(w, w, s); }
        swsq[k] = s;
    }
    __syncthreads();

    float* outq   = out;
    float* outidx = out + (size_t)NROWS * DD + 1;

    float lsum_total = 0.f;

    for (int row = blockIdx.x * TPB + tid; row < NROWS; row += GRID * TPB) {
        // ---- load row, compute mean / unbiased std (two-pass, like reference) ----
        const float4* xr = (const float4*)(x + (size_t)row * DD);
        float4 v[16];
        float sum = 0.f;
        #pragma unroll
        for (int j = 0; j < 16; j++) {
            v[j] = xr[j];
            sum += (v[j].x + v[j].y) + (v[j].z + v[j].w);
        }
        float mean = sum * (1.0f / 64.0f);
        float sumd2 = 0.f;
        #pragma unroll
        for (int j = 0; j < 16; j++) {
            float d0 = v[j].x - mean, d1 = v[j].y - mean;
            float d2 = v[j].z - mean, d3 = v[j].w - mean;
            sumd2 = fmaf(d0, d0, sumd2);
            sumd2 = fmaf(d1, d1, sumd2);
            sumd2 = fmaf(d2, d2, sumd2);
            sumd2 = fmaf(d3, d3, sumd2);
        }
        float var    = __fdiv_rn(sumd2, 63.0f);          // ddof=1
        float stdev  = __fsqrt_rn(var);                   // IEEE sqrt
        float denorm = __fadd_rn(stdev, EPSF);
        float inv    = __frcp_rn(denorm);                 // precise reciprocal

        // ---- normalized row packed as 32 f32x2 regs; A = ||xn||^2 ----
        unsigned long long xn2[32];
        float A = 0.f;
        #pragma unroll
        for (int j = 0; j < 16; j++) {
            float x0 = (v[j].x - mean) * inv;
            float x1 = (v[j].y - mean) * inv;
            float x2 = (v[j].z - mean) * inv;
            float x3 = (v[j].w - mean) * inv;
            A = fmaf(x0, x0, A);
            A = fmaf(x1, x1, A);
            A = fmaf(x2, x2, A);
            A = fmaf(x3, x3, A);
            xn2[2 * j]     = pack2(x0, x1);
            xn2[2 * j + 1] = pack2(x2, x3);
        }

        // ---- argmin over 512 codes, emulating reference rounding:
        //      d_k = fl( fl(A + ||W_k||^2) - fl(2 * xn.W_k) )
        //      (explicit _rn intrinsics: no FMA contraction allowed here)
        float best = 3.4e38f;
        int   bi   = 0;
        const ulonglong2* sW2 = (const ulonglong2*)sW;
        for (int k = 0; k < KK; k++) {
            unsigned long long a0 = 0ull, a1 = 0ull, a2 = 0ull, a3 = 0ull;
            const ulonglong2* wp = sW2 + k * (DD / 4);
            #pragma unroll
            for (int j = 0; j < 16; j += 2) {
                ulonglong2 wA = wp[j];       // 4 floats, LDS.128 broadcast
                ulonglong2 wB = wp[j + 1];
                ffma2(a0, xn2[2 * j],     wA.x);
                ffma2(a1, xn2[2 * j + 1], wA.y);
                ffma2(a2, xn2[2 * j + 2], wB.x);
                ffma2(a3, xn2[2 * j + 3], wB.y);
            }
            unsigned long long s = fadd2(fadd2(a0, a1), fadd2(a2, a3));
            float lo, hi; unpack2(s, lo, hi);
            float dot   = __fadd_rn(lo, hi);
            float Xk    = __fadd_rn(A, swsq[k]);          // fl(A + b_k)
            float dk    = __fsub_rn(Xk, __fmul_rn(2.0f, dot));  // fl(X - 2c)
            if (dk < best) { best = dk; bi = k; }         // first-min on ties
        }

        // ---- epilogue: quantized output, local loss, index ----
        const float4* wq = (const float4*)(sW + bi * DD);
        float4* oq = (float4*)(outq + (size_t)row * DD);
        float lsum = 0.f;
        #pragma unroll
        for (int j = 0; j < 16; j++) {
            float4 w = wq[j];
            float x0, x1, x2, x3;
            unpack2(xn2[2 * j],     x0, x1);
            unpack2(xn2[2 * j + 1], x2, x3);
            float d0 = w.x - x0, d1 = w.y - x1, d2 = w.z - x2, d3 = w.w - x3;
            lsum = fmaf(d0, d0, lsum);
            lsum = fmaf(d1, d1, lsum);
            lsum = fmaf(d2, d2, lsum);
            lsum = fmaf(d3, d3, lsum);
            float4 o;
            o.x = fmaf(w.x, denorm, mean);
            o.y = fmaf(w.y, denorm, mean);
            o.z = fmaf(w.z, denorm, mean);
            o.w = fmaf(w.w, denorm, mean);
            oq[j] = o;
        }
        lsum_total += lsum;
        outidx[row] = (float)bi;
    }

    // ---- deterministic block reduction of loss partials ----
    sred[tid] = lsum_total;
    __syncthreads();
    for (int s = TPB / 2; s > 0; s >>= 1) {
        if (tid < s) sred[tid] += sred[tid + s];
        __syncthreads();
    }
    if (tid == 0) g_partial[blockIdx.x] = sred[0];
}

__global__ void vq_loss(float* __restrict__ out)
{
    // single-thread deterministic reduction of 148 partials in double
    double t = 0.0;
    #pragma unroll 1
    for (int i = 0; i < GRID; i++) t += (double)g_partial[i];
    out[(size_t)NROWS * DD] = (float)(1.25 * t / (double)((size_t)NROWS * DD));
}

extern "C" void kernel_launch(void* const* d_in, const int* in_sizes, int n_in,
                              void* d_out, int out_size)
{
    const float* x = (const float*)d_in[0];
    const float* W = (const float*)d_in[1];
    float* out = (float*)d_out;

    cudaFuncSetAttribute(vq_main, cudaFuncAttributeMaxDynamicSharedMemorySize, SMEM_BYTES);
    vq_main<<<GRID, TPB, SMEM_BYTES>>>(x, W, out);
    vq_loss<<<1, 1>>>(out);
}